// round 16
// baseline (speedup 1.0000x reference)
#include <cuda_runtime.h>
#include <cuda_fp16.h>
#include <math.h>
#include <stdint.h>

#define BATCH 8
#define SEQ   1024
#define DM    1024
#define NH    16
#define HD    64
#define MTOT  (BATCH*SEQ)   // 8192

// Scratch (allocation-free)
__device__ __half g_hXq[MTOT*DM];
__device__ __half g_hXk[MTOT*DM];
__device__ __half g_hXv[MTOT*DM];
__device__ __half g_hWq[DM*DM];     // fp16 weights, row-major [k][n]
__device__ __half g_hWk[DM*DM];
__device__ __half g_hWv[DM*DM];
__device__ __half g_hWo[DM*DM];
__device__ __half g_Q  [MTOT*DM];
__device__ __half g_K  [MTOT*DM];
__device__ __half g_V  [MTOT*DM];
__device__ __half g_AO [MTOT*DM];

// ---------------------------------------------------------------------------
// primitives
// ---------------------------------------------------------------------------
__device__ __forceinline__ void mma_f16(float* c, const uint32_t* a, const uint32_t* b) {
    asm volatile(
        "mma.sync.aligned.m16n8k16.row.col.f32.f16.f16.f32 "
        "{%0,%1,%2,%3}, {%4,%5,%6,%7}, {%8,%9}, {%0,%1,%2,%3};"
        : "+f"(c[0]), "+f"(c[1]), "+f"(c[2]), "+f"(c[3])
        : "r"(a[0]), "r"(a[1]), "r"(a[2]), "r"(a[3]), "r"(b[0]), "r"(b[1]));
}

__device__ __forceinline__ void ldsm_x4(uint32_t* r, uint32_t addr) {
    asm volatile("ldmatrix.sync.aligned.m8n8.x4.shared.b16 {%0,%1,%2,%3}, [%4];"
        : "=r"(r[0]), "=r"(r[1]), "=r"(r[2]), "=r"(r[3]) : "r"(addr));
}

__device__ __forceinline__ void ldsm_x4_t(uint32_t* r, uint32_t addr) {
    asm volatile("ldmatrix.sync.aligned.m8n8.x4.trans.shared.b16 {%0,%1,%2,%3}, [%4];"
        : "=r"(r[0]), "=r"(r[1]), "=r"(r[2]), "=r"(r[3]) : "r"(addr));
}

__device__ __forceinline__ uint32_t packh2(float a, float b) {
    __half2 h = __floats2half2_rn(a, b);
    return *reinterpret_cast<uint32_t*>(&h);
}

// ---------------------------------------------------------------------------
// Prep: ONE fused fp32->fp16 convert over all 7 tensors (segment table).
// ---------------------------------------------------------------------------
struct ConvAll {
    const float4* s[7];
    __half2*      d[7];
    int           n4[7];
};

__global__ void conv_all_kernel(ConvAll p)
{
    int z = blockIdx.y;
    int n4 = p.n4[z];
    for (int i = blockIdx.x * blockDim.x + threadIdx.x; i < n4;
         i += gridDim.x * blockDim.x) {
        float4 v = p.s[z][i];
        p.d[z][2 * i]     = __floats2half2_rn(v.x, v.y);
        p.d[z][2 * i + 1] = __floats2half2_rn(v.z, v.w);
    }
}

// ---------------------------------------------------------------------------
// fp16 tensor-core GEMM core: C[M,N] = A @ W + bias; A [M][K], W [K][N] fp16.
// BM=128 BN=128 BK=64, 256 threads, warp 64x32, mma.m16n8k16.
// 3-stage cp.async pipeline, ONE __syncthreads per iteration, CORRECT order:
//   wait_group <=1  ->  barrier  ->  prefetch stage (it+2)%3  ->  compute it%3
// (prefetch AFTER the barrier: stage (it+2)%3 == (it-1)%3 and its readers
//  from iter it-1 have all crossed this barrier.)
// ---------------------------------------------------------------------------
#define GA_B (128*144)
#define GB_B (64*272)
#define GSTAGE (GA_B + GB_B)        // 35840
#define GEMM_SMEM (3*GSTAGE)        // 107520

__device__ __forceinline__ void g_load(const __half* __restrict__ A,
                                       const __half* __restrict__ W,
                                       uint32_t smA, uint32_t smB,
                                       int bm0, int bn0, int k0, int tid)
{
#pragma unroll
    for (int i = 0; i < 4; i++) {
        int id   = tid * 4 + i;
        int row  = id >> 3;
        int part = id & 7;
        const __half* ag = A + (size_t)(bm0 + row) * DM + k0 + part * 8;
        asm volatile("cp.async.ca.shared.global [%0], [%1], 16;"
                     :: "r"(smA + (uint32_t)row * 144u + (uint32_t)part * 16u), "l"(ag));
    }
#pragma unroll
    for (int i = 0; i < 4; i++) {
        int id   = tid * 4 + i;
        int row  = id >> 4;
        int part = id & 15;
        const __half* bg = W + (size_t)(k0 + row) * DM + bn0 + part * 8;
        asm volatile("cp.async.ca.shared.global [%0], [%1], 16;"
                     :: "r"(smB + (uint32_t)row * 272u + (uint32_t)part * 16u), "l"(bg));
    }
    asm volatile("cp.async.commit_group;");
}

template<bool HOUT>
__device__ __forceinline__ void gemm_core(
    const __half* __restrict__ A, const __half* __restrict__ W,
    const float* __restrict__ bias, void* __restrict__ Cout)
{
    extern __shared__ char smraw[];
    uint32_t smem_u = (uint32_t)__cvta_generic_to_shared(smraw);

    const int tid  = threadIdx.x;
    const int lane = tid & 31;
    const int wid  = tid >> 5;
    const int wm   = (wid >> 2) * 64;
    const int wn   = (wid & 3) * 32;
    const int g    = lane >> 2;
    const int t    = lane & 3;
    const int bm0  = blockIdx.y * 128;
    const int bn0  = blockIdx.x * 128;

    float c[4][4][4];
#pragma unroll
    for (int mt = 0; mt < 4; mt++)
#pragma unroll
        for (int nt = 0; nt < 4; nt++)
#pragma unroll
            for (int r = 0; r < 4; r++) c[mt][nt][r] = 0.f;

    const int NK = DM / 64;   // 16
    uint32_t st[3] = {smem_u, smem_u + GSTAGE, smem_u + 2 * GSTAGE};
    g_load(A, W, st[0], st[0] + GA_B, bm0, bn0, 0, tid);
    g_load(A, W, st[1], st[1] + GA_B, bm0, bn0, 64, tid);

    for (int it = 0; it < NK; it++) {
        // ensure stage it%3 arrived (<=1 group may remain in flight)
        if (it + 1 < NK) asm volatile("cp.async.wait_group 1;" ::: "memory");
        else             asm volatile("cp.async.wait_group 0;" ::: "memory");
        __syncthreads();   // data visible to all; all warps done with iter it-1

        if (it + 2 < NK)   // safe: previous readers of this stage crossed the barrier
            g_load(A, W, st[(it + 2) % 3], st[(it + 2) % 3] + GA_B,
                   bm0, bn0, (it + 2) * 64, tid);

        uint32_t sa = st[it % 3];
        uint32_t sb = sa + GA_B;

#pragma unroll
        for (int ks = 0; ks < 4; ks++) {
            uint32_t af[4][4], bf[4][2];
#pragma unroll
            for (int mt = 0; mt < 4; mt++)
                ldsm_x4(af[mt], sa + (uint32_t)(wm + mt * 16 + (lane & 15)) * 144u
                              + (uint32_t)(ks * 16 + (lane >> 4) * 8) * 2u);
#pragma unroll
            for (int np = 0; np < 2; np++) {
                uint32_t tmp[4];
                ldsm_x4_t(tmp, sb + (uint32_t)(ks * 16 + (lane & 7) + ((lane & 8) ? 8 : 0)) * 272u
                             + (uint32_t)(wn + np * 16 + ((lane & 16) ? 8 : 0)) * 2u);
                bf[2 * np][0]     = tmp[0]; bf[2 * np][1]     = tmp[1];
                bf[2 * np + 1][0] = tmp[2]; bf[2 * np + 1][1] = tmp[3];
            }
#pragma unroll
            for (int mt = 0; mt < 4; mt++)
#pragma unroll
                for (int nt = 0; nt < 4; nt++)
                    mma_f16(c[mt][nt], af[mt], bf[nt]);
        }
    }

#pragma unroll
    for (int mt = 0; mt < 4; mt++) {
        int r0 = bm0 + wm + mt * 16 + g;
#pragma unroll
        for (int nt = 0; nt < 4; nt++) {
            int cc = bn0 + wn + nt * 8 + 2 * t;
            float b0 = bias[cc], b1 = bias[cc + 1];
            if (HOUT) {
                __half* C = (__half*)Cout;
                *reinterpret_cast<__half2*>(C + (size_t)r0 * DM + cc) =
                    __floats2half2_rn(c[mt][nt][0] + b0, c[mt][nt][1] + b1);
                *reinterpret_cast<__half2*>(C + (size_t)(r0 + 8) * DM + cc) =
                    __floats2half2_rn(c[mt][nt][2] + b0, c[mt][nt][3] + b1);
            } else {
                float* C = (float*)Cout;
                float2 v0 = {c[mt][nt][0] + b0, c[mt][nt][1] + b1};
                float2 v1 = {c[mt][nt][2] + b0, c[mt][nt][3] + b1};
                *reinterpret_cast<float2*>(C + (size_t)r0 * DM + cc)       = v0;
                *reinterpret_cast<float2*>(C + (size_t)(r0 + 8) * DM + cc) = v1;
            }
        }
    }
}

struct GemmBatch {
    const __half* A[3];
    const __half* W[3];
    const float*  b[3];
    __half*       C[3];
};

__global__ __launch_bounds__(256, 2) void gemm_qkv_kernel(GemmBatch gb)
{
    int z = blockIdx.z;
    gemm_core<true>(gb.A[z], gb.W[z], gb.b[z], gb.C[z]);
}

__global__ __launch_bounds__(256, 2) void gemm_out_kernel(
    const __half* __restrict__ A, const __half* __restrict__ W,
    const float* __restrict__ bias, float* __restrict__ C)
{
    gemm_core<false>(A, W, bias, C);
}

// ---------------------------------------------------------------------------
// fp16 flash attention: fixed-reference softmax, register-resident P,
// hoisted Q fragments, 3-stage cp.async KV pipeline, single barrier per
// iteration with the corrected wait->barrier->prefetch ordering.
// ---------------------------------------------------------------------------
#define BR 128
#define BC 64
#define AST 72
#define KVBUF_B (2 * BC * AST * 2)                  // K+V one stage: 18432 B
#define ATTN_SMEM ((BR*AST)*2 + 3*KVBUF_B)          // Qs + 3 KV stages = 73728 B

#define C2 0.045084220027780107f   // (1/32) * log2(e)

__global__ __launch_bounds__(256, 2) void attn_f16_kernel()
{
    extern __shared__ __half smh[];
    __half* Qs = smh;                               // [128][72]
    uint32_t qs_u = (uint32_t)__cvta_generic_to_shared(Qs);
    uint32_t kv_u = qs_u + BR * AST * 2;            // 3 stages of (K, V) [64][72]

    const int qb   = blockIdx.x;
    const int h    = blockIdx.y;
    const int b    = blockIdx.z;
    const int tid  = threadIdx.x;
    const int lane = tid & 31;
    const int wid  = tid >> 5;
    const int g    = lane >> 2;
    const int t    = lane & 3;
    const int wrow = wid * 16;

    const __half* Qg = g_Q  + (size_t)(b * SEQ + qb * BR) * DM + h * HD;
    const __half* Kg = g_K  + (size_t)(b * SEQ) * DM + h * HD;
    const __half* Vg = g_V  + (size_t)(b * SEQ) * DM + h * HD;
    __half*       Og = g_AO + (size_t)(b * SEQ + qb * BR) * DM + h * HD;

    // Load Q block [128][64]
#pragma unroll
    for (int it = 0; it < 4; it++) {
        int idx  = tid + it * 256;
        int r    = idx >> 3;
        int part = idx & 7;
        *reinterpret_cast<uint4*>(&Qs[r * AST + part * 8]) =
            *reinterpret_cast<const uint4*>(Qg + (size_t)r * DM + part * 8);
    }

#define KV_LOAD(kb, stage)                                                      \
    do {                                                                        \
        uint32_t kbuf = kv_u + (uint32_t)(stage) * KVBUF_B;                     \
        uint32_t vbuf = kbuf + BC * AST * 2;                                    \
        _Pragma("unroll")                                                       \
        for (int i = 0; i < 2; i++) {                                           \
            int idx  = tid + i * 256;                                           \
            int j    = idx >> 3;                                                \
            int part = idx & 7;                                                 \
            uint32_t so = (uint32_t)j * 144u + (uint32_t)part * 16u;            \
            asm volatile("cp.async.ca.shared.global [%0], [%1], 16;"            \
                :: "r"(kbuf + so), "l"(Kg + (size_t)((kb) * BC + j) * DM + part * 8)); \
            asm volatile("cp.async.ca.shared.global [%0], [%1], 16;"            \
                :: "r"(vbuf + so), "l"(Vg + (size_t)((kb) * BC + j) * DM + part * 8)); \
        }                                                                       \
        asm volatile("cp.async.commit_group;");                                \
    } while (0)

    KV_LOAD(0, 0);
    KV_LOAD(1, 1);
    __syncthreads();   // Qs stores visible to all warps

    // Hoisted loop-invariant Q fragments
    uint32_t qf[4][4];
#pragma unroll
    for (int ks = 0; ks < 4; ks++)
        ldsm_x4(qf[ks], qs_u + (uint32_t)(wrow + (lane & 15)) * 144u
                      + (uint32_t)(ks * 16 + (lane >> 4) * 8) * 2u);

    float o[8][4];
#pragma unroll
    for (int nt = 0; nt < 8; nt++)
#pragma unroll
        for (int r = 0; r < 4; r++) o[nt][r] = 0.f;
    float l0 = 0.f, l1 = 0.f;

    const int NKB = SEQ / BC;   // 16
    for (int kb = 0; kb < NKB; kb++) {
        // ensure stage kb%3 arrived (<=1 group in flight afterwards)
        if (kb + 1 < NKB) asm volatile("cp.async.wait_group 1;" ::: "memory");
        else              asm volatile("cp.async.wait_group 0;" ::: "memory");
        __syncthreads();   // all warps done with iter kb-1; data visible

        if (kb + 2 < NKB)   // safe after the barrier (see gemm_core comment)
            KV_LOAD(kb + 2, (kb + 2) % 3);

        uint32_t ks_u = kv_u + (uint32_t)(kb % 3) * KVBUF_B;
        uint32_t vs_u = ks_u + BC * AST * 2;

        // ---- S = Q @ K^T ----
        float s[8][4];
#pragma unroll
        for (int nt = 0; nt < 8; nt++)
#pragma unroll
            for (int r = 0; r < 4; r++) s[nt][r] = 0.f;

#pragma unroll
        for (int ks = 0; ks < 4; ks++) {
#pragma unroll
            for (int np = 0; np < 4; np++) {
                uint32_t tmp[4];
                ldsm_x4(tmp, ks_u + (uint32_t)(np * 16 + (lane & 7) + ((lane & 16) ? 8 : 0)) * 144u
                           + (uint32_t)(ks * 16 + ((lane & 8) ? 8 : 0)) * 2u);
                mma_f16(s[2 * np],     qf[ks], tmp);
                mma_f16(s[2 * np + 1], qf[ks], tmp + 2);
            }
        }

        // ---- fixed-reference softmax + pack P into A-fragments ----
        uint32_t pf[4][4];
#pragma unroll
        for (int np = 0; np < 4; np++) {
            float e00 = exp2f(s[2 * np][0] * C2);
            float e01 = exp2f(s[2 * np][1] * C2);
            float e02 = exp2f(s[2 * np][2] * C2);
            float e03 = exp2f(s[2 * np][3] * C2);
            float e10 = exp2f(s[2 * np + 1][0] * C2);
            float e11 = exp2f(s[2 * np + 1][1] * C2);
            float e12 = exp2f(s[2 * np + 1][2] * C2);
            float e13 = exp2f(s[2 * np + 1][3] * C2);
            l0 += (e00 + e01) + (e10 + e11);
            l1 += (e02 + e03) + (e12 + e13);
            pf[np][0] = packh2(e00, e01);
            pf[np][1] = packh2(e02, e03);
            pf[np][2] = packh2(e10, e11);
            pf[np][3] = packh2(e12, e13);
        }

        // ---- O += P @ V ----
#pragma unroll
        for (int np = 0; np < 4; np++) {
#pragma unroll
            for (int vn = 0; vn < 4; vn++) {
                uint32_t tmp[4];
                ldsm_x4_t(tmp, vs_u + (uint32_t)(np * 16 + (lane & 7) + ((lane & 8) ? 8 : 0)) * 144u
                             + (uint32_t)(vn * 16 + ((lane & 16) ? 8 : 0)) * 2u);
                mma_f16(o[2 * vn],     pf[np], tmp);
                mma_f16(o[2 * vn + 1], pf[np], tmp + 2);
            }
        }
    }
#undef KV_LOAD

    // Deferred row-sum reduction, normalize, write
    l0 += __shfl_xor_sync(0xffffffffu, l0, 1);
    l0 += __shfl_xor_sync(0xffffffffu, l0, 2);
    l1 += __shfl_xor_sync(0xffffffffu, l1, 1);
    l1 += __shfl_xor_sync(0xffffffffu, l1, 2);
    float inv0 = 1.f / l0, inv1 = 1.f / l1;
    __half* o0 = Og + (size_t)(wrow + g) * DM;
    __half* o1 = Og + (size_t)(wrow + g + 8) * DM;
#pragma unroll
    for (int nt = 0; nt < 8; nt++) {
        int cc = nt * 8 + 2 * t;
        *reinterpret_cast<__half2*>(o0 + cc) =
            __floats2half2_rn(o[nt][0] * inv0, o[nt][1] * inv0);
        *reinterpret_cast<__half2*>(o1 + cc) =
            __floats2half2_rn(o[nt][2] * inv1, o[nt][3] * inv1);
    }
}

// ---------------------------------------------------------------------------
extern "C" void kernel_launch(void* const* d_in, const int* in_sizes, int n_in,
                              void* d_out, int out_size)
{
    const float* query = (const float*)d_in[0];
    const float* key   = (const float*)d_in[1];
    const float* value = (const float*)d_in[2];
    const float* Wq    = (const float*)d_in[3];
    const float* bq    = (const float*)d_in[4];
    const float* Wk    = (const float*)d_in[5];
    const float* bk    = (const float*)d_in[6];
    const float* Wv    = (const float*)d_in[7];
    const float* bv    = (const float*)d_in[8];
    const float* Wo    = (const float*)d_in[9];
    const float* bo    = (const float*)d_in[10];
    float* out = (float*)d_out;

    __half *hXq, *hXk, *hXv, *hWq, *hWk, *hWv, *hWo, *Qp, *Kp, *Vp, *AOp;
    cudaGetSymbolAddress((void**)&hXq, g_hXq);
    cudaGetSymbolAddress((void**)&hXk, g_hXk);
    cudaGetSymbolAddress((void**)&hXv, g_hXv);
    cudaGetSymbolAddress((void**)&hWq, g_hWq);
    cudaGetSymbolAddress((void**)&hWk, g_hWk);
    cudaGetSymbolAddress((void**)&hWv, g_hWv);
    cudaGetSymbolAddress((void**)&hWo, g_hWo);
    cudaGetSymbolAddress((void**)&Qp,  g_Q);
    cudaGetSymbolAddress((void**)&Kp,  g_K);
    cudaGetSymbolAddress((void**)&Vp,  g_V);
    cudaGetSymbolAddress((void**)&AOp, g_AO);

    // Prep: one fused convert launch
    int n4a = MTOT * DM / 4;
    int n4w = DM * DM / 4;
    ConvAll ca;
    ca.s[0] = (const float4*)query; ca.d[0] = (__half2*)hXq; ca.n4[0] = n4a;
    ca.s[1] = (const float4*)key;   ca.d[1] = (__half2*)hXk; ca.n4[1] = n4a;
    ca.s[2] = (const float4*)value; ca.d[2] = (__half2*)hXv; ca.n4[2] = n4a;
    ca.s[3] = (const float4*)Wq;    ca.d[3] = (__half2*)hWq; ca.n4[3] = n4w;
    ca.s[4] = (const float4*)Wk;    ca.d[4] = (__half2*)hWk; ca.n4[4] = n4w;
    ca.s[5] = (const float4*)Wv;    ca.d[5] = (__half2*)hWv; ca.n4[5] = n4w;
    ca.s[6] = (const float4*)Wo;    ca.d[6] = (__half2*)hWo; ca.n4[6] = n4w;
    conv_all_kernel<<<dim3(1024, 7), 256>>>(ca);

    // Q/K/V projections in one launch
    GemmBatch gb;
    gb.A[0] = hXq; gb.W[0] = hWq; gb.b[0] = bq; gb.C[0] = Qp;
    gb.A[1] = hXk; gb.W[1] = hWk; gb.b[1] = bk; gb.C[1] = Kp;
    gb.A[2] = hXv; gb.W[2] = hWv; gb.b[2] = bv; gb.C[2] = Vp;
    cudaFuncSetAttribute(gemm_qkv_kernel,
                         cudaFuncAttributeMaxDynamicSharedMemorySize, GEMM_SMEM);
    cudaFuncSetAttribute(gemm_out_kernel,
                         cudaFuncAttributeMaxDynamicSharedMemorySize, GEMM_SMEM);
    gemm_qkv_kernel<<<dim3(DM / 128, MTOT / 128, 3), 256, GEMM_SMEM>>>(gb);

    cudaFuncSetAttribute(attn_f16_kernel,
                         cudaFuncAttributeMaxDynamicSharedMemorySize, ATTN_SMEM);
    attn_f16_kernel<<<dim3(SEQ / BR, NH, BATCH), 256, ATTN_SMEM>>>();

    gemm_out_kernel<<<dim3(DM / 128, MTOT / 128), 256, GEMM_SMEM>>>(AOp, hWo, bo, out);
}

// round 17
// speedup vs baseline: 1.3702x; 1.3702x over previous
#include <cuda_runtime.h>
#include <cuda_fp16.h>
#include <math.h>
#include <stdint.h>

#define BATCH 8
#define SEQ   1024
#define DM    1024
#define NH    16
#define HD    64
#define MTOT  (BATCH*SEQ)   // 8192

// Scratch (allocation-free)
__device__ __half g_hXq[MTOT*DM];
__device__ __half g_hXk[MTOT*DM];
__device__ __half g_hXv[MTOT*DM];
__device__ __half g_hWq[DM*DM];     // fp16 weights, row-major [k][n]
__device__ __half g_hWk[DM*DM];
__device__ __half g_hWv[DM*DM];
__device__ __half g_hWo[DM*DM];
__device__ __half g_Q  [MTOT*DM];
__device__ __half g_K  [MTOT*DM];
__device__ __half g_V  [MTOT*DM];
__device__ __half g_AO [MTOT*DM];

// ---------------------------------------------------------------------------
// primitives
// ---------------------------------------------------------------------------
__device__ __forceinline__ void mma_f16(float* c, const uint32_t* a, const uint32_t* b) {
    asm volatile(
        "mma.sync.aligned.m16n8k16.row.col.f32.f16.f16.f32 "
        "{%0,%1,%2,%3}, {%4,%5,%6,%7}, {%8,%9}, {%0,%1,%2,%3};"
        : "+f"(c[0]), "+f"(c[1]), "+f"(c[2]), "+f"(c[3])
        : "r"(a[0]), "r"(a[1]), "r"(a[2]), "r"(a[3]), "r"(b[0]), "r"(b[1]));
}

__device__ __forceinline__ void ldsm_x4(uint32_t* r, uint32_t addr) {
    asm volatile("ldmatrix.sync.aligned.m8n8.x4.shared.b16 {%0,%1,%2,%3}, [%4];"
        : "=r"(r[0]), "=r"(r[1]), "=r"(r[2]), "=r"(r[3]) : "r"(addr));
}

__device__ __forceinline__ void ldsm_x4_t(uint32_t* r, uint32_t addr) {
    asm volatile("ldmatrix.sync.aligned.m8n8.x4.trans.shared.b16 {%0,%1,%2,%3}, [%4];"
        : "=r"(r[0]), "=r"(r[1]), "=r"(r[2]), "=r"(r[3]) : "r"(addr));
}

__device__ __forceinline__ uint32_t packh2(float a, float b) {
    __half2 h = __floats2half2_rn(a, b);
    return *reinterpret_cast<uint32_t*>(&h);
}

// ---------------------------------------------------------------------------
// Prep: ONE fused fp32->fp16 convert over all 7 tensors (segment table).
// ---------------------------------------------------------------------------
struct ConvAll {
    const float4* s[7];
    __half2*      d[7];
    int           n4[7];
};

__global__ void conv_all_kernel(ConvAll p)
{
    int z = blockIdx.y;
    int n4 = p.n4[z];
    for (int i = blockIdx.x * blockDim.x + threadIdx.x; i < n4;
         i += gridDim.x * blockDim.x) {
        float4 v = p.s[z][i];
        p.d[z][2 * i]     = __floats2half2_rn(v.x, v.y);
        p.d[z][2 * i + 1] = __floats2half2_rn(v.z, v.w);
    }
}

// ---------------------------------------------------------------------------
// fp16 tensor-core GEMM: C[M,N] = A @ W + bias; A [M][K], W [K][N] fp16.
// BM=128 BN=128 BK=64, 128 threads (4 warps, 2x2), WARP TILE 64x64,
// mma.m16n8k16, R14-proven 2-stage cp.async pipeline (2 barriers/iter).
// Warp tile 64x64 halves smem bytes/MAC vs 64x32 (smem-BW was the binding
// limit per R16 ncu: L1 62.6%, DRAM 2.6%).
// A stride 72 halfs, B stride 136 halfs (both ==4 mod 32 words) -> conflict-free.
// ---------------------------------------------------------------------------
#define GA_B (128*144)
#define GB_B (64*272)
#define GSTAGE (GA_B + GB_B)        // 35840
#define GEMM_SMEM (2*GSTAGE)        // 71680

__device__ __forceinline__ void g_load(const __half* __restrict__ A,
                                       const __half* __restrict__ W,
                                       uint32_t smA, uint32_t smB,
                                       int bm0, int bn0, int k0, int tid)
{
    // A tile: 128 rows x 64 halfs; 8 threads cover one 128B row
#pragma unroll
    for (int i = 0; i < 8; i++) {
        int row  = (tid >> 3) + i * 16;
        int part = tid & 7;
        const __half* ag = A + (size_t)(bm0 + row) * DM + k0 + part * 8;
        asm volatile("cp.async.ca.shared.global [%0], [%1], 16;"
                     :: "r"(smA + (uint32_t)row * 144u + (uint32_t)part * 16u), "l"(ag));
    }
    // B tile: 64 k-rows x 128 halfs; 16 threads cover one 256B row
#pragma unroll
    for (int i = 0; i < 8; i++) {
        int row  = (tid >> 4) + i * 8;
        int part = tid & 15;
        const __half* bg = W + (size_t)(k0 + row) * DM + bn0 + part * 8;
        asm volatile("cp.async.ca.shared.global [%0], [%1], 16;"
                     :: "r"(smB + (uint32_t)row * 272u + (uint32_t)part * 16u), "l"(bg));
    }
    asm volatile("cp.async.commit_group;");
}

template<bool HOUT>
__device__ __forceinline__ void gemm_core(
    const __half* __restrict__ A, const __half* __restrict__ W,
    const float* __restrict__ bias, void* __restrict__ Cout)
{
    extern __shared__ char smraw[];
    uint32_t smem_u = (uint32_t)__cvta_generic_to_shared(smraw);

    const int tid  = threadIdx.x;
    const int lane = tid & 31;
    const int wid  = tid >> 5;           // 0..3
    const int wm   = (wid >> 1) * 64;    // warp row offset (0,64)
    const int wn   = (wid & 1) * 64;     // warp col offset (0,64)
    const int g    = lane >> 2;
    const int t    = lane & 3;
    const int bm0  = blockIdx.y * 128;
    const int bn0  = blockIdx.x * 128;

    float c[4][8][4];
#pragma unroll
    for (int mt = 0; mt < 4; mt++)
#pragma unroll
        for (int nt = 0; nt < 8; nt++)
#pragma unroll
            for (int r = 0; r < 4; r++) c[mt][nt][r] = 0.f;

    const int NK = DM / 64;   // 16
    uint32_t st0 = smem_u;
    uint32_t st1 = smem_u + GSTAGE;
    g_load(A, W, st0, st0 + GA_B, bm0, bn0, 0, tid);

    for (int it = 0; it < NK; it++) {
        if (it + 1 < NK) {
            uint32_t nb = ((it + 1) & 1) ? st1 : st0;
            g_load(A, W, nb, nb + GA_B, bm0, bn0, (it + 1) * 64, tid);
            asm volatile("cp.async.wait_group 1;" ::: "memory");
        } else {
            asm volatile("cp.async.wait_group 0;" ::: "memory");
        }
        __syncthreads();

        uint32_t sa = (it & 1) ? st1 : st0;
        uint32_t sb = sa + GA_B;

#pragma unroll
        for (int ks = 0; ks < 4; ks++) {
            uint32_t af[4][4], bf[8][2];
#pragma unroll
            for (int mt = 0; mt < 4; mt++)
                ldsm_x4(af[mt], sa + (uint32_t)(wm + mt * 16 + (lane & 15)) * 144u
                              + (uint32_t)(ks * 16 + (lane >> 4) * 8) * 2u);
#pragma unroll
            for (int np = 0; np < 4; np++) {
                uint32_t tmp[4];
                ldsm_x4_t(tmp, sb + (uint32_t)(ks * 16 + (lane & 7) + ((lane & 8) ? 8 : 0)) * 272u
                             + (uint32_t)(wn + np * 16 + ((lane & 16) ? 8 : 0)) * 2u);
                bf[2 * np][0]     = tmp[0]; bf[2 * np][1]     = tmp[1];
                bf[2 * np + 1][0] = tmp[2]; bf[2 * np + 1][1] = tmp[3];
            }
#pragma unroll
            for (int mt = 0; mt < 4; mt++)
#pragma unroll
                for (int nt = 0; nt < 8; nt++)
                    mma_f16(c[mt][nt], af[mt], bf[nt]);
        }
        __syncthreads();
    }

#pragma unroll
    for (int mt = 0; mt < 4; mt++) {
        int r0 = bm0 + wm + mt * 16 + g;
#pragma unroll
        for (int nt = 0; nt < 8; nt++) {
            int cc = bn0 + wn + nt * 8 + 2 * t;
            float b0 = bias[cc], b1 = bias[cc + 1];
            if (HOUT) {
                __half* C = (__half*)Cout;
                *reinterpret_cast<__half2*>(C + (size_t)r0 * DM + cc) =
                    __floats2half2_rn(c[mt][nt][0] + b0, c[mt][nt][1] + b1);
                *reinterpret_cast<__half2*>(C + (size_t)(r0 + 8) * DM + cc) =
                    __floats2half2_rn(c[mt][nt][2] + b0, c[mt][nt][3] + b1);
            } else {
                float* C = (float*)Cout;
                float2 v0 = {c[mt][nt][0] + b0, c[mt][nt][1] + b1};
                float2 v1 = {c[mt][nt][2] + b0, c[mt][nt][3] + b1};
                *reinterpret_cast<float2*>(C + (size_t)r0 * DM + cc)       = v0;
                *reinterpret_cast<float2*>(C + (size_t)(r0 + 8) * DM + cc) = v1;
            }
        }
    }
}

struct GemmBatch {
    const __half* A[3];
    const __half* W[3];
    const float*  b[3];
    __half*       C[3];
};

__global__ __launch_bounds__(128, 2) void gemm_qkv_kernel(GemmBatch gb)
{
    int z = blockIdx.z;
    gemm_core<true>(gb.A[z], gb.W[z], gb.b[z], gb.C[z]);
}

__global__ __launch_bounds__(128, 2) void gemm_out_kernel(
    const __half* __restrict__ A, const __half* __restrict__ W,
    const float* __restrict__ bias, float* __restrict__ C)
{
    gemm_core<false>(A, W, bias, C);
}

// ---------------------------------------------------------------------------
// fp16 flash attention — EXACT R14 structure (proven 104.8us):
// fixed-reference softmax, register-resident P, hoisted Q fragments,
// 2-stage cp.async KV pipeline with 2 barriers per iteration.
// ---------------------------------------------------------------------------
#define BR 128
#define BC 64
#define AST 72
#define KVBUF_B (2 * BC * AST * 2)                  // K+V one stage: 18432 B
#define ATTN_SMEM ((BR*AST)*2 + 2*KVBUF_B)          // Qs + 2 KV stages = 55296 B

#define C2 0.045084220027780107f   // (1/32) * log2(e)

__global__ __launch_bounds__(256, 2) void attn_f16_kernel()
{
    extern __shared__ __half smh[];
    __half* Qs = smh;                               // [128][72]
    uint32_t qs_u = (uint32_t)__cvta_generic_to_shared(Qs);
    uint32_t kv_u = qs_u + BR * AST * 2;            // 2 stages of (K, V) [64][72]

    const int qb   = blockIdx.x;
    const int h    = blockIdx.y;
    const int b    = blockIdx.z;
    const int tid  = threadIdx.x;
    const int lane = tid & 31;
    const int wid  = tid >> 5;
    const int g    = lane >> 2;
    const int t    = lane & 3;
    const int wrow = wid * 16;

    const __half* Qg = g_Q  + (size_t)(b * SEQ + qb * BR) * DM + h * HD;
    const __half* Kg = g_K  + (size_t)(b * SEQ) * DM + h * HD;
    const __half* Vg = g_V  + (size_t)(b * SEQ) * DM + h * HD;
    __half*       Og = g_AO + (size_t)(b * SEQ + qb * BR) * DM + h * HD;

    // Load Q block [128][64]
#pragma unroll
    for (int it = 0; it < 4; it++) {
        int idx  = tid + it * 256;
        int r    = idx >> 3;
        int part = idx & 7;
        *reinterpret_cast<uint4*>(&Qs[r * AST + part * 8]) =
            *reinterpret_cast<const uint4*>(Qg + (size_t)r * DM + part * 8);
    }

#define KV_LOAD(kb, stage)                                                      \
    do {                                                                        \
        uint32_t kbuf = kv_u + (uint32_t)(stage) * KVBUF_B;                     \
        uint32_t vbuf = kbuf + BC * AST * 2;                                    \
        _Pragma("unroll")                                                       \
        for (int i = 0; i < 2; i++) {                                           \
            int idx  = tid + i * 256;                                           \
            int j    = idx >> 3;                                                \
            int part = idx & 7;                                                 \
            uint32_t so = (uint32_t)j * 144u + (uint32_t)part * 16u;            \
            asm volatile("cp.async.ca.shared.global [%0], [%1], 16;"            \
                :: "r"(kbuf + so), "l"(Kg + (size_t)((kb) * BC + j) * DM + part * 8)); \
            asm volatile("cp.async.ca.shared.global [%0], [%1], 16;"            \
                :: "r"(vbuf + so), "l"(Vg + (size_t)((kb) * BC + j) * DM + part * 8)); \
        }                                                                       \
        asm volatile("cp.async.commit_group;");                                \
    } while (0)

    KV_LOAD(0, 0);
    __syncthreads();   // Qs visible to all warps

    // Hoisted loop-invariant Q fragments
    uint32_t qf[4][4];
#pragma unroll
    for (int ks = 0; ks < 4; ks++)
        ldsm_x4(qf[ks], qs_u + (uint32_t)(wrow + (lane & 15)) * 144u
                      + (uint32_t)(ks * 16 + (lane >> 4) * 8) * 2u);

    float o[8][4];
#pragma unroll
    for (int nt = 0; nt < 8; nt++)
#pragma unroll
        for (int r = 0; r < 4; r++) o[nt][r] = 0.f;
    float l0 = 0.f, l1 = 0.f;

    const int NKB = SEQ / BC;   // 16
    for (int kb = 0; kb < NKB; kb++) {
        __syncthreads();   // all warps done with the stage we're about to overwrite
        if (kb + 1 < NKB) {
            KV_LOAD(kb + 1, (kb + 1) & 1);
            asm volatile("cp.async.wait_group 1;" ::: "memory");
        } else {
            asm volatile("cp.async.wait_group 0;" ::: "memory");
        }
        __syncthreads();

        uint32_t ks_u = kv_u + (uint32_t)(kb & 1) * KVBUF_B;
        uint32_t vs_u = ks_u + BC * AST * 2;

        // ---- S = Q @ K^T ----
        float s[8][4];
#pragma unroll
        for (int nt = 0; nt < 8; nt++)
#pragma unroll
            for (int r = 0; r < 4; r++) s[nt][r] = 0.f;

#pragma unroll
        for (int ks = 0; ks < 4; ks++) {
#pragma unroll
            for (int np = 0; np < 4; np++) {
                uint32_t tmp[4];
                ldsm_x4(tmp, ks_u + (uint32_t)(np * 16 + (lane & 7) + ((lane & 16) ? 8 : 0)) * 144u
                           + (uint32_t)(ks * 16 + ((lane & 8) ? 8 : 0)) * 2u);
                mma_f16(s[2 * np],     qf[ks], tmp);
                mma_f16(s[2 * np + 1], qf[ks], tmp + 2);
            }
        }

        // ---- fixed-reference softmax + pack P into A-fragments ----
        uint32_t pf[4][4];
#pragma unroll
        for (int np = 0; np < 4; np++) {
            float e00 = exp2f(s[2 * np][0] * C2);
            float e01 = exp2f(s[2 * np][1] * C2);
            float e02 = exp2f(s[2 * np][2] * C2);
            float e03 = exp2f(s[2 * np][3] * C2);
            float e10 = exp2f(s[2 * np + 1][0] * C2);
            float e11 = exp2f(s[2 * np + 1][1] * C2);
            float e12 = exp2f(s[2 * np + 1][2] * C2);
            float e13 = exp2f(s[2 * np + 1][3] * C2);
            l0 += (e00 + e01) + (e10 + e11);
            l1 += (e02 + e03) + (e12 + e13);
            pf[np][0] = packh2(e00, e01);
            pf[np][1] = packh2(e02, e03);
            pf[np][2] = packh2(e10, e11);
            pf[np][3] = packh2(e12, e13);
        }

        // ---- O += P @ V ----
#pragma unroll
        for (int np = 0; np < 4; np++) {
#pragma unroll
            for (int vn = 0; vn < 4; vn++) {
                uint32_t tmp[4];
                ldsm_x4_t(tmp, vs_u + (uint32_t)(np * 16 + (lane & 7) + ((lane & 8) ? 8 : 0)) * 144u
                             + (uint32_t)(vn * 16 + ((lane & 16) ? 8 : 0)) * 2u);
                mma_f16(o[2 * vn],     pf[np], tmp);
                mma_f16(o[2 * vn + 1], pf[np], tmp + 2);
            }
        }
    }
#undef KV_LOAD

    // Deferred row-sum reduction, normalize, write
    l0 += __shfl_xor_sync(0xffffffffu, l0, 1);
    l0 += __shfl_xor_sync(0xffffffffu, l0, 2);
    l1 += __shfl_xor_sync(0xffffffffu, l1, 1);
    l1 += __shfl_xor_sync(0xffffffffu, l1, 2);
    float inv0 = 1.f / l0, inv1 = 1.f / l1;
    __half* o0 = Og + (size_t)(wrow + g) * DM;
    __half* o1 = Og + (size_t)(wrow + g + 8) * DM;
#pragma unroll
    for (int nt = 0; nt < 8; nt++) {
        int cc = nt * 8 + 2 * t;
        *reinterpret_cast<__half2*>(o0 + cc) =
            __floats2half2_rn(o[nt][0] * inv0, o[nt][1] * inv0);
        *reinterpret_cast<__half2*>(o1 + cc) =
            __floats2half2_rn(o[nt][2] * inv1, o[nt][3] * inv1);
    }
}

// ---------------------------------------------------------------------------
extern "C" void kernel_launch(void* const* d_in, const int* in_sizes, int n_in,
                              void* d_out, int out_size)
{
    const float* query = (const float*)d_in[0];
    const float* key   = (const float*)d_in[1];
    const float* value = (const float*)d_in[2];
    const float* Wq    = (const float*)d_in[3];
    const float* bq    = (const float*)d_in[4];
    const float* Wk    = (const float*)d_in[5];
    const float* bk    = (const float*)d_in[6];
    const float* Wv    = (const float*)d_in[7];
    const float* bv    = (const float*)d_in[8];
    const float* Wo    = (const float*)d_in[9];
    const float* bo    = (const float*)d_in[10];
    float* out = (float*)d_out;

    __half *hXq, *hXk, *hXv, *hWq, *hWk, *hWv, *hWo, *Qp, *Kp, *Vp, *AOp;
    cudaGetSymbolAddress((void**)&hXq, g_hXq);
    cudaGetSymbolAddress((void**)&hXk, g_hXk);
    cudaGetSymbolAddress((void**)&hXv, g_hXv);
    cudaGetSymbolAddress((void**)&hWq, g_hWq);
    cudaGetSymbolAddress((void**)&hWk, g_hWk);
    cudaGetSymbolAddress((void**)&hWv, g_hWv);
    cudaGetSymbolAddress((void**)&hWo, g_hWo);
    cudaGetSymbolAddress((void**)&Qp,  g_Q);
    cudaGetSymbolAddress((void**)&Kp,  g_K);
    cudaGetSymbolAddress((void**)&Vp,  g_V);
    cudaGetSymbolAddress((void**)&AOp, g_AO);

    // Prep: one fused convert launch
    int n4a = MTOT * DM / 4;
    int n4w = DM * DM / 4;
    ConvAll ca;
    ca.s[0] = (const float4*)query; ca.d[0] = (__half2*)hXq; ca.n4[0] = n4a;
    ca.s[1] = (const float4*)key;   ca.d[1] = (__half2*)hXk; ca.n4[1] = n4a;
    ca.s[2] = (const float4*)value; ca.d[2] = (__half2*)hXv; ca.n4[2] = n4a;
    ca.s[3] = (const float4*)Wq;    ca.d[3] = (__half2*)hWq; ca.n4[3] = n4w;
    ca.s[4] = (const float4*)Wk;    ca.d[4] = (__half2*)hWk; ca.n4[4] = n4w;
    ca.s[5] = (const float4*)Wv;    ca.d[5] = (__half2*)hWv; ca.n4[5] = n4w;
    ca.s[6] = (const float4*)Wo;    ca.d[6] = (__half2*)hWo; ca.n4[6] = n4w;
    conv_all_kernel<<<dim3(1024, 7), 256>>>(ca);

    // Q/K/V projections in one launch (128-thread CTAs, warp tile 64x64)
    GemmBatch gb;
    gb.A[0] = hXq; gb.W[0] = hWq; gb.b[0] = bq; gb.C[0] = Qp;
    gb.A[1] = hXk; gb.W[1] = hWk; gb.b[1] = bk; gb.C[1] = Kp;
    gb.A[2] = hXv; gb.W[2] = hWv; gb.b[2] = bv; gb.C[2] = Vp;
    cudaFuncSetAttribute(gemm_qkv_kernel,
                         cudaFuncAttributeMaxDynamicSharedMemorySize, GEMM_SMEM);
    cudaFuncSetAttribute(gemm_out_kernel,
                         cudaFuncAttributeMaxDynamicSharedMemorySize, GEMM_SMEM);
    gemm_qkv_kernel<<<dim3(DM / 128, MTOT / 128, 3), 128, GEMM_SMEM>>>(gb);

    cudaFuncSetAttribute(attn_f16_kernel,
                         cudaFuncAttributeMaxDynamicSharedMemorySize, ATTN_SMEM);
    attn_f16_kernel<<<dim3(SEQ / BR, NH, BATCH), 256, ATTN_SMEM>>>();

    gemm_out_kernel<<<dim3(DM / 128, MTOT / 128), 128, GEMM_SMEM>>>(AOp, hWo, bo, out);
}